// round 2
// baseline (speedup 1.0000x reference)
#include <cuda_runtime.h>
#include <cstdint>
#include <cstddef>

#define IN_DIM   1024
#define HID_DIM  512
#define OUT_DIM  1024
#define N_EXP    6
#define H3       (N_EXP * HID_DIM)   // 3072
#define MAXB     32768

// Scratch (device globals — no allocation allowed in kernel_launch)
__device__ float g_gate[(size_t)MAXB * N_EXP];          // [B,6]
__device__ float g_hs[(size_t)MAXB * H3];               // [B,3072] gated hidden

// ---------------------------------------------------------------------------
// Gate kernel: one warp per token.
// alpha = sigmoid(x.g2w + g2b); gate3 = softmax(x.g3w + g3b)
// gate[b, i2*3 + j3] = gate2[i2] * gate3[j3]
// ---------------------------------------------------------------------------
__global__ __launch_bounds__(256) void gate_kernel(
    const float* __restrict__ x,
    const float* __restrict__ g2w, const float* __restrict__ g2b,
    const float* __restrict__ g3w, const float* __restrict__ g3b,
    float* __restrict__ gate, int B)
{
    int warp = (blockIdx.x * blockDim.x + threadIdx.x) >> 5;
    int lane = threadIdx.x & 31;
    if (warp >= B) return;

    const float4* xr = reinterpret_cast<const float4*>(x + (size_t)warp * IN_DIM);
    float a0 = 0.f, a1 = 0.f, a2 = 0.f, a3 = 0.f;
    #pragma unroll 4
    for (int i = lane; i < IN_DIM / 4; i += 32) {
        float4 v = xr[i];
        int k = i * 4;
        a0 += v.x * g2w[k] + v.y * g2w[k + 1] + v.z * g2w[k + 2] + v.w * g2w[k + 3];
        a1 += v.x * g3w[(k)*3 + 0] + v.y * g3w[(k+1)*3 + 0] + v.z * g3w[(k+2)*3 + 0] + v.w * g3w[(k+3)*3 + 0];
        a2 += v.x * g3w[(k)*3 + 1] + v.y * g3w[(k+1)*3 + 1] + v.z * g3w[(k+2)*3 + 1] + v.w * g3w[(k+3)*3 + 1];
        a3 += v.x * g3w[(k)*3 + 2] + v.y * g3w[(k+1)*3 + 2] + v.z * g3w[(k+2)*3 + 2] + v.w * g3w[(k+3)*3 + 2];
    }
    #pragma unroll
    for (int off = 16; off > 0; off >>= 1) {
        a0 += __shfl_down_sync(0xffffffffu, a0, off);
        a1 += __shfl_down_sync(0xffffffffu, a1, off);
        a2 += __shfl_down_sync(0xffffffffu, a2, off);
        a3 += __shfl_down_sync(0xffffffffu, a3, off);
    }
    if (lane == 0) {
        float s2 = a0 + g2b[0];
        float alpha = 1.f / (1.f + expf(-s2));
        float l0 = a1 + g3b[0], l1 = a2 + g3b[1], l2 = a3 + g3b[2];
        float m = fmaxf(l0, fmaxf(l1, l2));
        float e0 = expf(l0 - m), e1 = expf(l1 - m), e2 = expf(l2 - m);
        float inv = 1.f / (e0 + e1 + e2);
        float p0 = e0 * inv, p1 = e1 * inv, p2 = e2 * inv;
        float ga = 1.f - alpha;
        float* o = gate + (size_t)warp * N_EXP;
        o[0] = ga * p0;    o[1] = ga * p1;    o[2] = ga * p2;
        o[3] = alpha * p0; o[4] = alpha * p1; o[5] = alpha * p2;
    }
}

// ---------------------------------------------------------------------------
// Tiled fp32 GEMM with packed fma.rn.f32x2 inner loop (2x FFMA rate on sm_103a).
// BM=BN=128, BK=16, 256 threads, 8x8 per thread (accumulators held as f32x2 pairs).
//
// FIRST = true : C[B,3072] = relu(x @ W1cat + b1cat) * gate   (W1 = [6,1024,512])
// FIRST = false: C[B,1024] = Hs @ W2cat + gate @ b2           (W2 = [3072,1024])
// ---------------------------------------------------------------------------
template <int K, bool FIRST>
__global__ __launch_bounds__(256) void moe_gemm(
    const float* __restrict__ A,     // [B, K] row-major, lda == K
    const float* __restrict__ W,
    const float* __restrict__ bias,  // b1 [6,512] or b2 [6,1024]
    const float* __restrict__ gate,  // [B,6]
    float* __restrict__ C, int ldc)
{
    constexpr int BM = 128, BN = 128, BK = 16;
    constexpr int S = FIRST ? HID_DIM : OUT_DIM;   // W row stride

    __shared__ float As[BK][BM];
    __shared__ float Bs[BK][BN];

    const int tid = threadIdx.x;
    const int rowBlk = blockIdx.x * BM;   // x-major over rows => W tile reused across wave
    const int colBlk = blockIdx.y * BN;
    const int tx = tid & 15, ty = tid >> 4;

    const int e = colBlk >> 9;            // expert id (only used when FIRST)
    const float* Bp;
    if (FIRST) Bp = W + (size_t)e * IN_DIM * HID_DIM + (colBlk & 511);
    else       Bp = W + colBlk;

    const int aRow = tid >> 2;
    const int aCol4 = (tid & 3) << 2;

    unsigned long long acc2[8][4];
    #pragma unroll
    for (int i = 0; i < 8; i++)
        #pragma unroll
        for (int j = 0; j < 4; j++) acc2[i][j] = 0ull;

    for (int k0 = 0; k0 < K; k0 += BK) {
        // A tile [BM x BK] -> As[k][m] (transposed store)
        #pragma unroll
        for (int i = 0; i < 2; i++) {
            int r = aRow + i * 64;
            float4 v = *reinterpret_cast<const float4*>(
                A + (size_t)(rowBlk + r) * K + k0 + aCol4);
            As[aCol4 + 0][r] = v.x;
            As[aCol4 + 1][r] = v.y;
            As[aCol4 + 2][r] = v.z;
            As[aCol4 + 3][r] = v.w;
        }
        // B tile [BK x BN]
        #pragma unroll
        for (int i = 0; i < 2; i++) {
            int idx = tid + i * 256;
            int r = idx >> 5;
            int c4 = (idx & 31) << 2;
            *reinterpret_cast<float4*>(&Bs[r][c4]) =
                *reinterpret_cast<const float4*>(Bp + (size_t)(k0 + r) * S + c4);
        }
        __syncthreads();

        #pragma unroll
        for (int k = 0; k < BK; k++) {
            float4 ra0 = *reinterpret_cast<const float4*>(&As[k][ty * 8]);
            float4 ra1 = *reinterpret_cast<const float4*>(&As[k][ty * 8 + 4]);
            unsigned long long rb[4];
            #pragma unroll
            for (int j = 0; j < 4; j++)
                rb[j] = *reinterpret_cast<const unsigned long long*>(&Bs[k][tx * 8 + j * 2]);
            float ra[8] = {ra0.x, ra0.y, ra0.z, ra0.w, ra1.x, ra1.y, ra1.z, ra1.w};
            #pragma unroll
            for (int i = 0; i < 8; i++) {
                unsigned long long av;
                asm("mov.b64 %0, {%1, %1};" : "=l"(av) : "f"(ra[i]));
                #pragma unroll
                for (int j = 0; j < 4; j++)
                    asm("fma.rn.f32x2 %0, %1, %2, %0;"
                        : "+l"(acc2[i][j]) : "l"(av), "l"(rb[j]));
            }
        }
        __syncthreads();
    }

    // Epilogue
    #pragma unroll
    for (int i = 0; i < 8; i++) {
        int row = rowBlk + ty * 8 + i;
        float out[8];
        if (FIRST) {
            float g = gate[(size_t)row * N_EXP + e];
            #pragma unroll
            for (int j = 0; j < 4; j++) {
                float lo, hi;
                asm("mov.b64 {%0, %1}, %2;" : "=f"(lo), "=f"(hi) : "l"(acc2[i][j]));
                int h = (colBlk & 511) + tx * 8 + j * 2;   // local col within expert
                lo += bias[e * HID_DIM + h];
                hi += bias[e * HID_DIM + h + 1];
                out[j * 2]     = fmaxf(lo, 0.f) * g;
                out[j * 2 + 1] = fmaxf(hi, 0.f) * g;
            }
        } else {
            float gw[N_EXP];
            #pragma unroll
            for (int q = 0; q < N_EXP; q++) gw[q] = gate[(size_t)row * N_EXP + q];
            #pragma unroll
            for (int j = 0; j < 4; j++) {
                float lo, hi;
                asm("mov.b64 {%0, %1}, %2;" : "=f"(lo), "=f"(hi) : "l"(acc2[i][j]));
                int c = colBlk + tx * 8 + j * 2;
                float blo = 0.f, bhi = 0.f;
                #pragma unroll
                for (int q = 0; q < N_EXP; q++) {
                    blo += gw[q] * bias[q * OUT_DIM + c];
                    bhi += gw[q] * bias[q * OUT_DIM + c + 1];
                }
                out[j * 2]     = lo + blo;
                out[j * 2 + 1] = hi + bhi;
            }
        }
        float* cp = C + (size_t)row * ldc + colBlk + tx * 8;
        *reinterpret_cast<float4*>(cp)     = make_float4(out[0], out[1], out[2], out[3]);
        *reinterpret_cast<float4*>(cp + 4) = make_float4(out[4], out[5], out[6], out[7]);
    }
}

// ---------------------------------------------------------------------------
extern "C" void kernel_launch(void* const* d_in, const int* in_sizes, int n_in,
                              void* d_out, int out_size)
{
    const float* x   = (const float*)d_in[0];
    const float* g2w = (const float*)d_in[1];
    const float* g2b = (const float*)d_in[2];
    const float* g3w = (const float*)d_in[3];
    const float* g3b = (const float*)d_in[4];
    const float* w1  = (const float*)d_in[5];
    const float* b1  = (const float*)d_in[6];
    const float* w2  = (const float*)d_in[7];
    const float* b2  = (const float*)d_in[8];
    float* out = (float*)d_out;

    const int B = in_sizes[0] / IN_DIM;   // 32768

    float* gate; float* hs;
    cudaGetSymbolAddress((void**)&gate, g_gate);
    cudaGetSymbolAddress((void**)&hs, g_hs);

    // 1) gate weights
    gate_kernel<<<(B + 7) / 8, 256>>>(x, g2w, g2b, g3w, g3b, gate, B);

    // 2) Hs = relu(x @ W1cat + b1) * gate   [B, 3072]
    {
        dim3 grid(B / 128, H3 / 128);
        moe_gemm<IN_DIM, true><<<grid, 256>>>(x, w1, b1, gate, hs, H3);
    }

    // 3) out = Hs @ W2cat + gate @ b2       [B, 1024]
    {
        dim3 grid(B / 128, OUT_DIM / 128);
        moe_gemm<H3, false><<<grid, 256>>>(hs, w2, b2, gate, out, OUT_DIM);
    }
}

// round 4
// speedup vs baseline: 2.9593x; 2.9593x over previous
#include <cuda_runtime.h>
#include <cuda_bf16.h>
#include <cstdint>
#include <cstddef>

#define IN_DIM   1024
#define HID_DIM  512
#define OUT_DIM  1024
#define N_EXP    6
#define H3       3072
#define MAXB     32768

// ---------------- scratch (device globals; no allocation allowed) ----------
__device__ float         g_gate[(size_t)MAXB * N_EXP];
__device__ __nv_bfloat16 g_xhi [(size_t)MAXB * IN_DIM];
__device__ __nv_bfloat16 g_xlo [(size_t)MAXB * IN_DIM];
__device__ __nv_bfloat16 g_w1hi[(size_t)H3 * IN_DIM];    // [3072,1024] N-major, K contig
__device__ __nv_bfloat16 g_w1lo[(size_t)H3 * IN_DIM];
__device__ __nv_bfloat16 g_w2hi[(size_t)OUT_DIM * H3];   // [1024,3072]
__device__ __nv_bfloat16 g_w2lo[(size_t)OUT_DIM * H3];
__device__ __nv_bfloat16 g_hshi[(size_t)MAXB * H3];
__device__ __nv_bfloat16 g_hslo[(size_t)MAXB * H3];

// ---------------- helpers ---------------------------------------------------
__device__ __forceinline__ uint32_t smem_u32(const void* p) {
    uint32_t a;
    asm("{ .reg .u64 t; cvta.to.shared.u64 t, %1; cvt.u32.u64 %0, t; }" : "=r"(a) : "l"(p));
    return a;
}
__device__ __forceinline__ void cp16(uint32_t dst, const void* src) {
    asm volatile("cp.async.cg.shared.global [%0], [%1], 16;" :: "r"(dst), "l"(src));
}
__device__ __forceinline__ void cp_commit() {
    asm volatile("cp.async.commit_group;" ::: "memory");
}
template <int N>
__device__ __forceinline__ void cp_wait() {
    asm volatile("cp.async.wait_group %0;" :: "n"(N) : "memory");
}
__device__ __forceinline__ void ldsm4(uint32_t* r, uint32_t addr) {
    asm volatile("ldmatrix.sync.aligned.m8n8.x4.shared.b16 {%0,%1,%2,%3}, [%4];"
                 : "=r"(r[0]), "=r"(r[1]), "=r"(r[2]), "=r"(r[3]) : "r"(addr));
}
__device__ __forceinline__ void mma_bf16(float* c, const uint32_t* a, const uint32_t* b) {
    asm volatile(
        "mma.sync.aligned.m16n8k16.row.col.f32.bf16.bf16.f32 "
        "{%0,%1,%2,%3}, {%4,%5,%6,%7}, {%8,%9}, {%0,%1,%2,%3};"
        : "+f"(c[0]), "+f"(c[1]), "+f"(c[2]), "+f"(c[3])
        : "r"(a[0]), "r"(a[1]), "r"(a[2]), "r"(a[3]), "r"(b[0]), "r"(b[1]));
}
// 64B rows, 16B chunks, xor-swizzle so any 8 consecutive rows at fixed chunk
// index hit 8 distinct 16B slots mod 128B (conflict-free ldmatrix).
__device__ __forceinline__ int sw_off(int row, int chunk) {
    return row * 64 + ((chunk ^ ((row >> 1) & 3)) << 4);
}

// ---------------- fused gate + x split (one pass over x) -------------------
__global__ __launch_bounds__(256) void gate_split_kernel(
    const float* __restrict__ x,
    const float* __restrict__ g2w, const float* __restrict__ g2b,
    const float* __restrict__ g3w, const float* __restrict__ g3b,
    float* __restrict__ gate,
    __nv_bfloat16* __restrict__ xhi, __nv_bfloat16* __restrict__ xlo, int B)
{
    int row  = (blockIdx.x * 256 + threadIdx.x) >> 5;
    int lane = threadIdx.x & 31;
    if (row >= B) return;

    const float4* xr = reinterpret_cast<const float4*>(x + (size_t)row * IN_DIM);
    float a0 = 0.f, a1 = 0.f, a2 = 0.f, a3 = 0.f;
    #pragma unroll
    for (int j = 0; j < 8; ++j) {
        int i = lane + j * 32;
        float4 v = xr[i];
        int k = i * 4;
        a0 = fmaf(v.x, g2w[k], fmaf(v.y, g2w[k+1], fmaf(v.z, g2w[k+2], fmaf(v.w, g2w[k+3], a0))));
        a1 = fmaf(v.x, g3w[k*3+0], fmaf(v.y, g3w[(k+1)*3+0], fmaf(v.z, g3w[(k+2)*3+0], fmaf(v.w, g3w[(k+3)*3+0], a1))));
        a2 = fmaf(v.x, g3w[k*3+1], fmaf(v.y, g3w[(k+1)*3+1], fmaf(v.z, g3w[(k+2)*3+1], fmaf(v.w, g3w[(k+3)*3+1], a2))));
        a3 = fmaf(v.x, g3w[k*3+2], fmaf(v.y, g3w[(k+1)*3+2], fmaf(v.z, g3w[(k+2)*3+2], fmaf(v.w, g3w[(k+3)*3+2], a3))));
        float vv[4] = {v.x, v.y, v.z, v.w};
        uint32_t ph[2], pl[2];
        #pragma unroll
        for (int q = 0; q < 2; ++q) {
            __nv_bfloat16 h0 = __float2bfloat16(vv[2*q]);
            __nv_bfloat16 h1 = __float2bfloat16(vv[2*q+1]);
            __nv_bfloat16 l0 = __float2bfloat16(vv[2*q]   - __bfloat162float(h0));
            __nv_bfloat16 l1 = __float2bfloat16(vv[2*q+1] - __bfloat162float(h1));
            ph[q] = (uint32_t)__bfloat16_as_ushort(h0) | ((uint32_t)__bfloat16_as_ushort(h1) << 16);
            pl[q] = (uint32_t)__bfloat16_as_ushort(l0) | ((uint32_t)__bfloat16_as_ushort(l1) << 16);
        }
        *reinterpret_cast<uint2*>(xhi + (size_t)row * IN_DIM + k) = make_uint2(ph[0], ph[1]);
        *reinterpret_cast<uint2*>(xlo + (size_t)row * IN_DIM + k) = make_uint2(pl[0], pl[1]);
    }
    #pragma unroll
    for (int off = 16; off > 0; off >>= 1) {
        a0 += __shfl_down_sync(0xffffffffu, a0, off);
        a1 += __shfl_down_sync(0xffffffffu, a1, off);
        a2 += __shfl_down_sync(0xffffffffu, a2, off);
        a3 += __shfl_down_sync(0xffffffffu, a3, off);
    }
    if (lane == 0) {
        float alpha = 1.f / (1.f + expf(-(a0 + g2b[0])));
        float l0 = a1 + g3b[0], l1 = a2 + g3b[1], l2 = a3 + g3b[2];
        float m = fmaxf(l0, fmaxf(l1, l2));
        float e0 = expf(l0 - m), e1 = expf(l1 - m), e2 = expf(l2 - m);
        float inv = 1.f / (e0 + e1 + e2);
        float p0 = e0 * inv, p1 = e1 * inv, p2 = e2 * inv, ga = 1.f - alpha;
        float* o = gate + (size_t)row * N_EXP;
        o[0] = ga * p0;    o[1] = ga * p1;    o[2] = ga * p2;
        o[3] = alpha * p0; o[4] = alpha * p1; o[5] = alpha * p2;
    }
}

// ---------------- transpose + split: src[R,C] fp32 -> dst[C,R] bf16 hi/lo --
__global__ void transplit_kernel(const float* __restrict__ src,
                                 __nv_bfloat16* __restrict__ dhi,
                                 __nv_bfloat16* __restrict__ dlo, int R, int C)
{
    __shared__ float t[32][33];
    size_t zoff = (size_t)blockIdx.z * R * C;
    int c0 = blockIdx.x * 32, r0 = blockIdx.y * 32;
    int tx = threadIdx.x, ty = threadIdx.y;          // 32 x 8
    #pragma unroll
    for (int i = 0; i < 4; ++i)
        t[ty + i*8][tx] = src[zoff + (size_t)(r0 + ty + i*8) * C + c0 + tx];
    __syncthreads();
    #pragma unroll
    for (int i = 0; i < 4; ++i) {
        int c = c0 + ty + i*8, r = r0 + tx;
        float v = t[tx][ty + i*8];
        __nv_bfloat16 h = __float2bfloat16(v);
        __nv_bfloat16 l = __float2bfloat16(v - __bfloat162float(h));
        dhi[zoff + (size_t)c * R + r] = h;
        dlo[zoff + (size_t)c * R + r] = l;
    }
}

// ---------------- split-bf16 HMMA GEMM (mma.sync, sm_103 baseline ISA) ------
// CTA tile 128x128, BK=32, 8 warps (2M x 4N), warp tile 64x32.
// acc += Ahi*Bhi + Ahi*Blo + Alo*Bhi per K-chunk, fp32 accum in registers.
// A [M,K] K-contig bf16 hi/lo; B(W) [N,K] K-contig bf16 hi/lo.
#define BM 128
#define BN 128
#define BK 32
#define STAGES 4
#define STAGE_BYTES 32768   // Ahi 8K | Alo 8K | Bhi 8K | Blo 8K
#define SMEM_TOTAL (STAGES * STAGE_BYTES)

template <int K, bool FIRST>
__global__ __launch_bounds__(256, 1) void gemm_mma(
    const __nv_bfloat16* __restrict__ Ahi, const __nv_bfloat16* __restrict__ Alo,
    const __nv_bfloat16* __restrict__ Bhi, const __nv_bfloat16* __restrict__ Blo,
    const float* __restrict__ bias, const float* __restrict__ gate,
    __nv_bfloat16* __restrict__ Chi, __nv_bfloat16* __restrict__ Clo,
    float* __restrict__ Cf)
{
    extern __shared__ char smem[];
    const uint32_t sbase = smem_u32(smem);
    const int tid  = threadIdx.x;
    const int wid  = tid >> 5;
    const int lane = tid & 31;
    const int mBlk = blockIdx.y * BM;
    const int nBlk = blockIdx.x * BN;
    const int wm = (wid >> 2) * 64;      // warp M offset in tile
    const int wn = (wid & 3) * 32;       // warp N offset in tile
    constexpr int NK = K / BK;

    // per-thread cp.async source/dest mapping (8 x 16B chunks per stage)
    // j<4 -> A region, j>=4 -> B region; idx in [0,1024): hl=idx>>9, row=(idx>>2)&127, c=idx&3
    const __nv_bfloat16* srcTab[4];
    srcTab[0] = Ahi + (size_t)mBlk * K;
    srcTab[1] = Alo + (size_t)mBlk * K;
    srcTab[2] = Bhi + (size_t)nBlk * K;
    srcTab[3] = Blo + (size_t)nBlk * K;

    float acc[4][4][4];
    #pragma unroll
    for (int i = 0; i < 4; ++i)
        #pragma unroll
        for (int j = 0; j < 4; ++j)
            #pragma unroll
            for (int q = 0; q < 4; ++q) acc[i][j][q] = 0.f;

    auto load_stage = [&](int s) {
        const int k0 = s * BK;
        const uint32_t sb = sbase + (s % STAGES) * STAGE_BYTES;
        #pragma unroll
        for (int j = 0; j < 8; ++j) {
            int idx = tid + (j & 3) * 256;           // 0..1023 within region
            int reg = (j >> 2) * 2 + (idx >> 9);     // 0..3: Ahi,Alo,Bhi,Blo
            int row = (idx >> 2) & 127;
            int c   = idx & 3;
            const __nv_bfloat16* src = srcTab[reg] + (size_t)row * K + k0 + c * 8;
            cp16(sb + reg * 8192 + sw_off(row, c), src);
        }
        cp_commit();
    };

    // prologue: stages 0..STAGES-2
    #pragma unroll
    for (int s = 0; s < STAGES - 1; ++s) load_stage(s);

    const int rA = wm + (lane & 15);                       // A ldmatrix row (per mi +16)
    const int rB = wn + ((lane >> 4) << 3) + (lane & 7);   // B ldmatrix row (per pair +16)
    const int cAoff = lane >> 4;                           // A chunk offset
    const int cBoff = (lane >> 3) & 1;                     // B chunk offset

    for (int s = 0; s < NK; ++s) {
        if (s + STAGES - 1 < NK) load_stage(s + STAGES - 1);
        else cp_commit();
        cp_wait<STAGES - 2>();
        __syncthreads();
        const uint32_t sb = sbase + (s % STAGES) * STAGE_BYTES;

        #pragma unroll
        for (int kk = 0; kk < 2; ++kk) {
            const int c = kk * 2;
            uint32_t Af[2][4][4];
            uint32_t Bf[2][4][2];
            #pragma unroll
            for (int hl = 0; hl < 2; ++hl) {
                #pragma unroll
                for (int mi = 0; mi < 4; ++mi) {
                    int r = rA + 16 * mi;
                    ldsm4(Af[hl][mi], sb + hl * 8192 + sw_off(r, c + cAoff));
                }
                #pragma unroll
                for (int jp = 0; jp < 2; ++jp) {
                    int r = rB + 16 * jp;
                    uint32_t t[4];
                    ldsm4(t, sb + 16384 + hl * 8192 + sw_off(r, c + cBoff));
                    Bf[hl][2*jp][0] = t[0]; Bf[hl][2*jp][1] = t[1];
                    Bf[hl][2*jp+1][0] = t[2]; Bf[hl][2*jp+1][1] = t[3];
                }
            }
            #pragma unroll
            for (int mi = 0; mi < 4; ++mi)
                #pragma unroll
                for (int nj = 0; nj < 4; ++nj) {
                    mma_bf16(acc[mi][nj], Af[0][mi], Bf[0][nj]);  // hi*hi
                    mma_bf16(acc[mi][nj], Af[0][mi], Bf[1][nj]);  // hi*lo
                    mma_bf16(acc[mi][nj], Af[1][mi], Bf[0][nj]);  // lo*hi
                }
        }
        __syncthreads();
    }

    // ---- epilogue ----
    if constexpr (FIRST) {
        const int e = nBlk >> 9;
        #pragma unroll
        for (int mi = 0; mi < 4; ++mi)
            #pragma unroll
            for (int h = 0; h < 2; ++h) {
                const int row = mBlk + wm + 16 * mi + (lane >> 2) + 8 * h;
                const float g = gate[(size_t)row * N_EXP + e];
                #pragma unroll
                for (int nj = 0; nj < 4; ++nj) {
                    const int col = nBlk + wn + 8 * nj + 2 * (lane & 3);
                    const int bc = e * HID_DIM + (col & (HID_DIM - 1));
                    float v0 = acc[mi][nj][2*h]   + bias[bc];
                    float v1 = acc[mi][nj][2*h+1] + bias[bc + 1];
                    v0 = fmaxf(v0, 0.f) * g;
                    v1 = fmaxf(v1, 0.f) * g;
                    __nv_bfloat16 h0 = __float2bfloat16(v0);
                    __nv_bfloat16 h1 = __float2bfloat16(v1);
                    __nv_bfloat16 l0 = __float2bfloat16(v0 - __bfloat162float(h0));
                    __nv_bfloat16 l1 = __float2bfloat16(v1 - __bfloat162float(h1));
                    uint32_t ph = (uint32_t)__bfloat16_as_ushort(h0) | ((uint32_t)__bfloat16_as_ushort(h1) << 16);
                    uint32_t pl = (uint32_t)__bfloat16_as_ushort(l0) | ((uint32_t)__bfloat16_as_ushort(l1) << 16);
                    *reinterpret_cast<uint32_t*>(Chi + (size_t)row * H3 + col) = ph;
                    *reinterpret_cast<uint32_t*>(Clo + (size_t)row * H3 + col) = pl;
                }
            }
    } else {
        #pragma unroll
        for (int mi = 0; mi < 4; ++mi)
            #pragma unroll
            for (int h = 0; h < 2; ++h) {
                const int row = mBlk + wm + 16 * mi + (lane >> 2) + 8 * h;
                float gw[N_EXP];
                #pragma unroll
                for (int q = 0; q < N_EXP; ++q) gw[q] = gate[(size_t)row * N_EXP + q];
                #pragma unroll
                for (int nj = 0; nj < 4; ++nj) {
                    const int col = nBlk + wn + 8 * nj + 2 * (lane & 3);
                    float v0 = acc[mi][nj][2*h];
                    float v1 = acc[mi][nj][2*h+1];
                    #pragma unroll
                    for (int q = 0; q < N_EXP; ++q) {
                        v0 = fmaf(gw[q], bias[q * OUT_DIM + col],     v0);
                        v1 = fmaf(gw[q], bias[q * OUT_DIM + col + 1], v1);
                    }
                    *reinterpret_cast<float2*>(Cf + (size_t)row * OUT_DIM + col) = make_float2(v0, v1);
                }
            }
    }
}

// ---------------------------------------------------------------------------
extern "C" void kernel_launch(void* const* d_in, const int* in_sizes, int n_in,
                              void* d_out, int out_size)
{
    const float* x   = (const float*)d_in[0];
    const float* g2w = (const float*)d_in[1];
    const float* g2b = (const float*)d_in[2];
    const float* g3w = (const float*)d_in[3];
    const float* g3b = (const float*)d_in[4];
    const float* w1  = (const float*)d_in[5];
    const float* b1  = (const float*)d_in[6];
    const float* w2  = (const float*)d_in[7];
    const float* b2  = (const float*)d_in[8];
    float* out = (float*)d_out;

    const int B = in_sizes[0] / IN_DIM;   // 32768

    float *gate; __nv_bfloat16 *xhi, *xlo, *w1hi, *w1lo, *w2hi, *w2lo, *hshi, *hslo;
    cudaGetSymbolAddress((void**)&gate, g_gate);
    cudaGetSymbolAddress((void**)&xhi, g_xhi);
    cudaGetSymbolAddress((void**)&xlo, g_xlo);
    cudaGetSymbolAddress((void**)&w1hi, g_w1hi);
    cudaGetSymbolAddress((void**)&w1lo, g_w1lo);
    cudaGetSymbolAddress((void**)&w2hi, g_w2hi);
    cudaGetSymbolAddress((void**)&w2lo, g_w2lo);
    cudaGetSymbolAddress((void**)&hshi, g_hshi);
    cudaGetSymbolAddress((void**)&hslo, g_hslo);

    cudaFuncSetAttribute(gemm_mma<IN_DIM, true>,
                         cudaFuncAttributeMaxDynamicSharedMemorySize, SMEM_TOTAL);
    cudaFuncSetAttribute(gemm_mma<H3, false>,
                         cudaFuncAttributeMaxDynamicSharedMemorySize, SMEM_TOTAL);

    // 1) gate + split x (single pass over x)
    gate_split_kernel<<<(B + 7) / 8, 256>>>(x, g2w, g2b, g3w, g3b, gate, xhi, xlo, B);

    // 2) transpose+split weights
    transplit_kernel<<<dim3(HID_DIM/32, IN_DIM/32, N_EXP), dim3(32, 8)>>>(w1, w1hi, w1lo, IN_DIM, HID_DIM);
    transplit_kernel<<<dim3(OUT_DIM/32, H3/32, 1),        dim3(32, 8)>>>(w2, w2hi, w2lo, H3, OUT_DIM);

    // 3) hs = split(relu(x @ W1 + b1) * gate)   [B,3072] bf16 hi/lo
    gemm_mma<IN_DIM, true><<<dim3(H3/BN, B/BM), 256, SMEM_TOTAL>>>(
        xhi, xlo, w1hi, w1lo, b1, gate, hshi, hslo, nullptr);

    // 4) out = hs @ W2 + gate @ b2              [B,1024] fp32
    gemm_mma<H3, false><<<dim3(OUT_DIM/BN, B/BM), 256, SMEM_TOTAL>>>(
        hshi, hslo, w2hi, w2lo, b2, gate, nullptr, nullptr, out);
}

// round 5
// speedup vs baseline: 3.0388x; 1.0269x over previous
#include <cuda_runtime.h>
#include <cuda_bf16.h>
#include <cstdint>
#include <cstddef>

#define IN_DIM   1024
#define HID_DIM  512
#define OUT_DIM  1024
#define N_EXP    6
#define H3       3072
#define MAXB     32768

// ---------------- scratch (device globals; no allocation allowed) ----------
__device__ float         g_gate[(size_t)MAXB * N_EXP];
__device__ __nv_bfloat16 g_xhi [(size_t)MAXB * IN_DIM];
__device__ __nv_bfloat16 g_xlo [(size_t)MAXB * IN_DIM];
__device__ __nv_bfloat16 g_w1hi[(size_t)H3 * IN_DIM];    // [3072,1024] N-major, K contig
__device__ __nv_bfloat16 g_w1lo[(size_t)H3 * IN_DIM];
__device__ __nv_bfloat16 g_w2hi[(size_t)OUT_DIM * H3];   // [1024,3072]
__device__ __nv_bfloat16 g_w2lo[(size_t)OUT_DIM * H3];
__device__ __nv_bfloat16 g_hshi[(size_t)MAXB * H3];
__device__ __nv_bfloat16 g_hslo[(size_t)MAXB * H3];

// ---------------- helpers ---------------------------------------------------
__device__ __forceinline__ uint32_t smem_u32(const void* p) {
    uint32_t a;
    asm("{ .reg .u64 t; cvta.to.shared.u64 t, %1; cvt.u32.u64 %0, t; }" : "=r"(a) : "l"(p));
    return a;
}
__device__ __forceinline__ void cp16(uint32_t dst, const void* src) {
    asm volatile("cp.async.cg.shared.global [%0], [%1], 16;" :: "r"(dst), "l"(src));
}
__device__ __forceinline__ void cp_commit() {
    asm volatile("cp.async.commit_group;" ::: "memory");
}
template <int N>
__device__ __forceinline__ void cp_wait() {
    asm volatile("cp.async.wait_group %0;" :: "n"(N) : "memory");
}
__device__ __forceinline__ void ldsm4(uint32_t* r, uint32_t addr) {
    asm volatile("ldmatrix.sync.aligned.m8n8.x4.shared.b16 {%0,%1,%2,%3}, [%4];"
                 : "=r"(r[0]), "=r"(r[1]), "=r"(r[2]), "=r"(r[3]) : "r"(addr));
}
__device__ __forceinline__ void mma_bf16(float* c, const uint32_t* a, const uint32_t* b) {
    asm volatile(
        "mma.sync.aligned.m16n8k16.row.col.f32.bf16.bf16.f32 "
        "{%0,%1,%2,%3}, {%4,%5,%6,%7}, {%8,%9}, {%0,%1,%2,%3};"
        : "+f"(c[0]), "+f"(c[1]), "+f"(c[2]), "+f"(c[3])
        : "r"(a[0]), "r"(a[1]), "r"(a[2]), "r"(a[3]), "r"(b[0]), "r"(b[1]));
}
// 64B rows, 16B chunks, xor-swizzle so any 8 consecutive rows at fixed chunk
// index hit 8 distinct 16B slots mod 128B (conflict-free ldmatrix).
__device__ __forceinline__ int sw_off(int row, int chunk) {
    return row * 64 + ((chunk ^ ((row >> 1) & 3)) << 4);
}

// ---------------- fused gate + x split (one pass over x) -------------------
__global__ __launch_bounds__(256) void gate_split_kernel(
    const float* __restrict__ x,
    const float* __restrict__ g2w, const float* __restrict__ g2b,
    const float* __restrict__ g3w, const float* __restrict__ g3b,
    float* __restrict__ gate,
    __nv_bfloat16* __restrict__ xhi, __nv_bfloat16* __restrict__ xlo, int B)
{
    int row  = (blockIdx.x * 256 + threadIdx.x) >> 5;
    int lane = threadIdx.x & 31;
    if (row >= B) return;

    const float4* xr = reinterpret_cast<const float4*>(x + (size_t)row * IN_DIM);
    float a0 = 0.f, a1 = 0.f, a2 = 0.f, a3 = 0.f;
    #pragma unroll
    for (int j = 0; j < 8; ++j) {
        int i = lane + j * 32;
        float4 v = xr[i];
        int k = i * 4;
        a0 = fmaf(v.x, g2w[k], fmaf(v.y, g2w[k+1], fmaf(v.z, g2w[k+2], fmaf(v.w, g2w[k+3], a0))));
        a1 = fmaf(v.x, g3w[k*3+0], fmaf(v.y, g3w[(k+1)*3+0], fmaf(v.z, g3w[(k+2)*3+0], fmaf(v.w, g3w[(k+3)*3+0], a1))));
        a2 = fmaf(v.x, g3w[k*3+1], fmaf(v.y, g3w[(k+1)*3+1], fmaf(v.z, g3w[(k+2)*3+1], fmaf(v.w, g3w[(k+3)*3+1], a2))));
        a3 = fmaf(v.x, g3w[k*3+2], fmaf(v.y, g3w[(k+1)*3+2], fmaf(v.z, g3w[(k+2)*3+2], fmaf(v.w, g3w[(k+3)*3+2], a3))));
        float vv[4] = {v.x, v.y, v.z, v.w};
        uint32_t ph[2], pl[2];
        #pragma unroll
        for (int q = 0; q < 2; ++q) {
            __nv_bfloat16 h0 = __float2bfloat16(vv[2*q]);
            __nv_bfloat16 h1 = __float2bfloat16(vv[2*q+1]);
            __nv_bfloat16 l0 = __float2bfloat16(vv[2*q]   - __bfloat162float(h0));
            __nv_bfloat16 l1 = __float2bfloat16(vv[2*q+1] - __bfloat162float(h1));
            ph[q] = (uint32_t)__bfloat16_as_ushort(h0) | ((uint32_t)__bfloat16_as_ushort(h1) << 16);
            pl[q] = (uint32_t)__bfloat16_as_ushort(l0) | ((uint32_t)__bfloat16_as_ushort(l1) << 16);
        }
        *reinterpret_cast<uint2*>(xhi + (size_t)row * IN_DIM + k) = make_uint2(ph[0], ph[1]);
        *reinterpret_cast<uint2*>(xlo + (size_t)row * IN_DIM + k) = make_uint2(pl[0], pl[1]);
    }
    #pragma unroll
    for (int off = 16; off > 0; off >>= 1) {
        a0 += __shfl_down_sync(0xffffffffu, a0, off);
        a1 += __shfl_down_sync(0xffffffffu, a1, off);
        a2 += __shfl_down_sync(0xffffffffu, a2, off);
        a3 += __shfl_down_sync(0xffffffffu, a3, off);
    }
    if (lane == 0) {
        float alpha = 1.f / (1.f + expf(-(a0 + g2b[0])));
        float l0 = a1 + g3b[0], l1 = a2 + g3b[1], l2 = a3 + g3b[2];
        float m = fmaxf(l0, fmaxf(l1, l2));
        float e0 = expf(l0 - m), e1 = expf(l1 - m), e2 = expf(l2 - m);
        float inv = 1.f / (e0 + e1 + e2);
        float p0 = e0 * inv, p1 = e1 * inv, p2 = e2 * inv, ga = 1.f - alpha;
        float* o = gate + (size_t)row * N_EXP;
        o[0] = ga * p0;    o[1] = ga * p1;    o[2] = ga * p2;
        o[3] = alpha * p0; o[4] = alpha * p1; o[5] = alpha * p2;
    }
}

// ---------------- transpose + split: src[R,C] fp32 -> dst[C,R] bf16 hi/lo --
__global__ void transplit_kernel(const float* __restrict__ src,
                                 __nv_bfloat16* __restrict__ dhi,
                                 __nv_bfloat16* __restrict__ dlo, int R, int C)
{
    __shared__ float t[32][33];
    size_t zoff = (size_t)blockIdx.z * R * C;
    int c0 = blockIdx.x * 32, r0 = blockIdx.y * 32;
    int tx = threadIdx.x, ty = threadIdx.y;          // 32 x 8
    #pragma unroll
    for (int i = 0; i < 4; ++i)
        t[ty + i*8][tx] = src[zoff + (size_t)(r0 + ty + i*8) * C + c0 + tx];
    __syncthreads();
    #pragma unroll
    for (int i = 0; i < 4; ++i) {
        int c = c0 + ty + i*8, r = r0 + tx;
        float v = t[tx][ty + i*8];
        __nv_bfloat16 h = __float2bfloat16(v);
        __nv_bfloat16 l = __float2bfloat16(v - __bfloat162float(h));
        dhi[zoff + (size_t)c * R + r] = h;
        dlo[zoff + (size_t)c * R + r] = l;
    }
}

// ---------------- split-bf16 HMMA GEMM (mma.sync) ---------------------------
// CTA tile 128x128, BK=32, 8 warps (2M x 4N), warp tile 64x32.
// acc += Ahi*Bhi + Ahi*Blo + Alo*Bhi per K-chunk, fp32 accum in registers.
// Single __syncthreads per K-iter; ldsm interleaved with MMA per pass.
#define BM 128
#define BN 128
#define BK 32
#define STAGES 4
#define STAGE_BYTES 32768   // Ahi 8K | Alo 8K | Bhi 8K | Blo 8K
#define SMEM_TOTAL (STAGES * STAGE_BYTES)

template <int K, bool FIRST>
__global__ __launch_bounds__(256, 1) void gemm_mma(
    const __nv_bfloat16* __restrict__ Ahi, const __nv_bfloat16* __restrict__ Alo,
    const __nv_bfloat16* __restrict__ Bhi, const __nv_bfloat16* __restrict__ Blo,
    const float* __restrict__ bias, const float* __restrict__ gate,
    __nv_bfloat16* __restrict__ Chi, __nv_bfloat16* __restrict__ Clo,
    float* __restrict__ Cf)
{
    extern __shared__ char smem[];
    const uint32_t sbase = smem_u32(smem);
    const int tid  = threadIdx.x;
    const int wid  = tid >> 5;
    const int lane = tid & 31;
    const int mBlk = blockIdx.y * BM;
    const int nBlk = blockIdx.x * BN;
    const int wm = (wid >> 2) * 64;      // warp M offset in tile
    const int wn = (wid & 3) * 32;       // warp N offset in tile
    constexpr int NK = K / BK;

    const __nv_bfloat16* srcTab[4];
    srcTab[0] = Ahi + (size_t)mBlk * K;
    srcTab[1] = Alo + (size_t)mBlk * K;
    srcTab[2] = Bhi + (size_t)nBlk * K;
    srcTab[3] = Blo + (size_t)nBlk * K;

    float acc[4][4][4];
    #pragma unroll
    for (int i = 0; i < 4; ++i)
        #pragma unroll
        for (int j = 0; j < 4; ++j)
            #pragma unroll
            for (int q = 0; q < 4; ++q) acc[i][j][q] = 0.f;

    auto load_stage = [&](int s) {
        const int k0 = s * BK;
        const uint32_t sb = sbase + (s % STAGES) * STAGE_BYTES;
        #pragma unroll
        for (int j = 0; j < 8; ++j) {
            int idx = tid + (j & 3) * 256;           // 0..1023 within region
            int reg = (j >> 2) * 2 + (idx >> 9);     // 0..3: Ahi,Alo,Bhi,Blo
            int row = (idx >> 2) & 127;
            int c   = idx & 3;
            const __nv_bfloat16* src = srcTab[reg] + (size_t)row * K + k0 + c * 8;
            cp16(sb + reg * 8192 + sw_off(row, c), src);
        }
        cp_commit();
    };

    // prologue: stages 0..STAGES-2
    #pragma unroll
    for (int s = 0; s < STAGES - 1; ++s) load_stage(s);

    const int rA = wm + (lane & 15);                       // A ldmatrix row (per mi +16)
    const int rB = wn + ((lane >> 4) << 3) + (lane & 7);   // B ldmatrix row (per pair +16)
    const int cAoff = lane >> 4;                           // A chunk offset
    const int cBoff = (lane >> 3) & 1;                     // B chunk offset

    for (int s = 0; s < NK; ++s) {
        cp_wait<STAGES - 2>();
        __syncthreads();
        // Issue next-stage loads immediately (runs under the MMA burst).
        // Writes slot (s-1)%STAGES, which the sync above just retired.
        if (s + STAGES - 1 < NK) load_stage(s + STAGES - 1);
        else cp_commit();                                   // keep group count uniform

        const uint32_t sb = sbase + (s % STAGES) * STAGE_BYTES;

        #pragma unroll
        for (int kk = 0; kk < 2; ++kk) {
            const int c = kk * 2;
            uint32_t Ah[4][4], Al[4][4], Bh[4][2], Bl[4][2];
            // hi fragments
            #pragma unroll
            for (int mi = 0; mi < 4; ++mi)
                ldsm4(Ah[mi], sb + sw_off(rA + 16 * mi, c + cAoff));
            #pragma unroll
            for (int jp = 0; jp < 2; ++jp) {
                uint32_t t[4];
                ldsm4(t, sb + 16384 + sw_off(rB + 16 * jp, c + cBoff));
                Bh[2*jp][0] = t[0]; Bh[2*jp][1] = t[1];
                Bh[2*jp+1][0] = t[2]; Bh[2*jp+1][1] = t[3];
            }
            // B lo fragments (independent of hi*hi MMAs below)
            #pragma unroll
            for (int jp = 0; jp < 2; ++jp) {
                uint32_t t[4];
                ldsm4(t, sb + 24576 + sw_off(rB + 16 * jp, c + cBoff));
                Bl[2*jp][0] = t[0]; Bl[2*jp][1] = t[1];
                Bl[2*jp+1][0] = t[2]; Bl[2*jp+1][1] = t[3];
            }
            // pass 1: hi*hi  (Al loads can be hoisted under these by ptxas)
            #pragma unroll
            for (int mi = 0; mi < 4; ++mi)
                #pragma unroll
                for (int nj = 0; nj < 4; ++nj)
                    mma_bf16(acc[mi][nj], Ah[mi], Bh[nj]);
            // A lo fragments
            #pragma unroll
            for (int mi = 0; mi < 4; ++mi)
                ldsm4(Al[mi], sb + 8192 + sw_off(rA + 16 * mi, c + cAoff));
            // pass 2: hi*lo
            #pragma unroll
            for (int mi = 0; mi < 4; ++mi)
                #pragma unroll
                for (int nj = 0; nj < 4; ++nj)
                    mma_bf16(acc[mi][nj], Ah[mi], Bl[nj]);
            // pass 3: lo*hi
            #pragma unroll
            for (int mi = 0; mi < 4; ++mi)
                #pragma unroll
                for (int nj = 0; nj < 4; ++nj)
                    mma_bf16(acc[mi][nj], Al[mi], Bh[nj]);
        }
        // NOTE: no trailing __syncthreads — next iteration's top sync is the
        // only barrier needed (loads in iter s+1 target slot s%STAGES only
        // after all warps pass that sync, i.e. after they finished reading it).
    }

    // ---- epilogue ----
    if constexpr (FIRST) {
        const int e = nBlk >> 9;
        #pragma unroll
        for (int mi = 0; mi < 4; ++mi)
            #pragma unroll
            for (int h = 0; h < 2; ++h) {
                const int row = mBlk + wm + 16 * mi + (lane >> 2) + 8 * h;
                const float g = gate[(size_t)row * N_EXP + e];
                #pragma unroll
                for (int nj = 0; nj < 4; ++nj) {
                    const int col = nBlk + wn + 8 * nj + 2 * (lane & 3);
                    const int bc = e * HID_DIM + (col & (HID_DIM - 1));
                    float v0 = acc[mi][nj][2*h]   + bias[bc];
                    float v1 = acc[mi][nj][2*h+1] + bias[bc + 1];
                    v0 = fmaxf(v0, 0.f) * g;
                    v1 = fmaxf(v1, 0.f) * g;
                    __nv_bfloat16 h0 = __float2bfloat16(v0);
                    __nv_bfloat16 h1 = __float2bfloat16(v1);
                    __nv_bfloat16 l0 = __float2bfloat16(v0 - __bfloat162float(h0));
                    __nv_bfloat16 l1 = __float2bfloat16(v1 - __bfloat162float(h1));
                    uint32_t ph = (uint32_t)__bfloat16_as_ushort(h0) | ((uint32_t)__bfloat16_as_ushort(h1) << 16);
                    uint32_t pl = (uint32_t)__bfloat16_as_ushort(l0) | ((uint32_t)__bfloat16_as_ushort(l1) << 16);
                    *reinterpret_cast<uint32_t*>(Chi + (size_t)row * H3 + col) = ph;
                    *reinterpret_cast<uint32_t*>(Clo + (size_t)row * H3 + col) = pl;
                }
            }
    } else {
        #pragma unroll
        for (int mi = 0; mi < 4; ++mi)
            #pragma unroll
            for (int h = 0; h < 2; ++h) {
                const int row = mBlk + wm + 16 * mi + (lane >> 2) + 8 * h;
                float gw[N_EXP];
                #pragma unroll
                for (int q = 0; q < N_EXP; ++q) gw[q] = gate[(size_t)row * N_EXP + q];
                #pragma unroll
                for (int nj = 0; nj < 4; ++nj) {
                    const int col = nBlk + wn + 8 * nj + 2 * (lane & 3);
                    float v0 = acc[mi][nj][2*h];
                    float v1 = acc[mi][nj][2*h+1];
                    #pragma unroll
                    for (int q = 0; q < N_EXP; ++q) {
                        v0 = fmaf(gw[q], bias[q * OUT_DIM + col],     v0);
                        v1 = fmaf(gw[q], bias[q * OUT_DIM + col + 1], v1);
                    }
                    *reinterpret_cast<float2*>(Cf + (size_t)row * OUT_DIM + col) = make_float2(v0, v1);
                }
            }
    }
}

// ---------------------------------------------------------------------------
extern "C" void kernel_launch(void* const* d_in, const int* in_sizes, int n_in,
                              void* d_out, int out_size)
{
    const float* x   = (const float*)d_in[0];
    const float* g2w = (const float*)d_in[1];
    const float* g2b = (const float*)d_in[2];
    const float* g3w = (const float*)d_in[3];
    const float* g3b = (const float*)d_in[4];
    const float* w1  = (const float*)d_in[5];
    const float* b1  = (const float*)d_in[6];
    const float* w2  = (const float*)d_in[7];
    const float* b2  = (const float*)d_in[8];
    float* out = (float*)d_out;

    const int B = in_sizes[0] / IN_DIM;   // 32768

    float *gate; __nv_bfloat16 *xhi, *xlo, *w1hi, *w1lo, *w2hi, *w2lo, *hshi, *hslo;
    cudaGetSymbolAddress((void**)&gate, g_gate);
    cudaGetSymbolAddress((void**)&xhi, g_xhi);
    cudaGetSymbolAddress((void**)&xlo, g_xlo);
    cudaGetSymbolAddress((void**)&w1hi, g_w1hi);
    cudaGetSymbolAddress((void**)&w1lo, g_w1lo);
    cudaGetSymbolAddress((void**)&w2hi, g_w2hi);
    cudaGetSymbolAddress((void**)&w2lo, g_w2lo);
    cudaGetSymbolAddress((void**)&hshi, g_hshi);
    cudaGetSymbolAddress((void**)&hslo, g_hslo);

    cudaFuncSetAttribute(gemm_mma<IN_DIM, true>,
                         cudaFuncAttributeMaxDynamicSharedMemorySize, SMEM_TOTAL);
    cudaFuncSetAttribute(gemm_mma<H3, false>,
                         cudaFuncAttributeMaxDynamicSharedMemorySize, SMEM_TOTAL);

    // 1) gate + split x (single pass over x)
    gate_split_kernel<<<(B + 7) / 8, 256>>>(x, g2w, g2b, g3w, g3b, gate, xhi, xlo, B);

    // 2) transpose+split weights
    transplit_kernel<<<dim3(HID_DIM/32, IN_DIM/32, N_EXP), dim3(32, 8)>>>(w1, w1hi, w1lo, IN_DIM, HID_DIM);
    transplit_kernel<<<dim3(OUT_DIM/32, H3/32, 1),        dim3(32, 8)>>>(w2, w2hi, w2lo, H3, OUT_DIM);

    // 3) hs = split(relu(x @ W1 + b1) * gate)   [B,3072] bf16 hi/lo
    gemm_mma<IN_DIM, true><<<dim3(H3/BN, B/BM), 256, SMEM_TOTAL>>>(
        xhi, xlo, w1hi, w1lo, b1, gate, hshi, hslo, nullptr);

    // 4) out = hs @ W2 + gate @ b2              [B,1024] fp32
    gemm_mma<H3, false><<<dim3(OUT_DIM/BN, B/BM), 256, SMEM_TOTAL>>>(
        hshi, hslo, w2hi, w2lo, b2, gate, nullptr, nullptr, out);
}

// round 6
// speedup vs baseline: 3.4169x; 1.1244x over previous
#include <cuda_runtime.h>
#include <cuda_bf16.h>
#include <cstdint>
#include <cstddef>

#define IN_DIM   1024
#define HID_DIM  512
#define OUT_DIM  1024
#define N_EXP    6
#define H3       3072
#define MAXB     32768

// ---------------- scratch (device globals; no allocation allowed) ----------
__device__ float         g_gate[(size_t)MAXB * N_EXP];
__device__ __nv_bfloat16 g_xhi [(size_t)MAXB * IN_DIM];
__device__ __nv_bfloat16 g_xlo [(size_t)MAXB * IN_DIM];
__device__ __nv_bfloat16 g_w1hi[(size_t)H3 * IN_DIM];    // [3072,1024] N-major, K contig
__device__ __nv_bfloat16 g_w1lo[(size_t)H3 * IN_DIM];
__device__ __nv_bfloat16 g_w2hi[(size_t)OUT_DIM * H3];   // [1024,3072]
__device__ __nv_bfloat16 g_w2lo[(size_t)OUT_DIM * H3];
__device__ __nv_bfloat16 g_hshi[(size_t)MAXB * H3];
__device__ __nv_bfloat16 g_hslo[(size_t)MAXB * H3];

// ---------------- helpers ---------------------------------------------------
__device__ __forceinline__ uint32_t smem_u32(const void* p) {
    uint32_t a;
    asm("{ .reg .u64 t; cvta.to.shared.u64 t, %1; cvt.u32.u64 %0, t; }" : "=r"(a) : "l"(p));
    return a;
}
__device__ __forceinline__ void cp16(uint32_t dst, const void* src) {
    asm volatile("cp.async.cg.shared.global [%0], [%1], 16;" :: "r"(dst), "l"(src));
}
__device__ __forceinline__ void cp_commit() {
    asm volatile("cp.async.commit_group;" ::: "memory");
}
template <int N>
__device__ __forceinline__ void cp_wait() {
    asm volatile("cp.async.wait_group %0;" :: "n"(N) : "memory");
}
__device__ __forceinline__ void ldsm4(uint32_t* r, uint32_t addr) {
    asm volatile("ldmatrix.sync.aligned.m8n8.x4.shared.b16 {%0,%1,%2,%3}, [%4];"
                 : "=r"(r[0]), "=r"(r[1]), "=r"(r[2]), "=r"(r[3]) : "r"(addr));
}
__device__ __forceinline__ void mma_bf16(float* c, const uint32_t* a, const uint32_t* b) {
    asm volatile(
        "mma.sync.aligned.m16n8k16.row.col.f32.bf16.bf16.f32 "
        "{%0,%1,%2,%3}, {%4,%5,%6,%7}, {%8,%9}, {%0,%1,%2,%3};"
        : "+f"(c[0]), "+f"(c[1]), "+f"(c[2]), "+f"(c[3])
        : "r"(a[0]), "r"(a[1]), "r"(a[2]), "r"(a[3]), "r"(b[0]), "r"(b[1]));
}
// 64B rows, 16B chunks, xor-swizzle so any 8 consecutive rows at fixed chunk
// index hit 8 distinct 16B slots mod 128B (conflict-free ldmatrix).
__device__ __forceinline__ int sw_off(int row, int chunk) {
    return row * 64 + ((chunk ^ ((row >> 1) & 3)) << 4);
}

// ---------------- fused gate + x split (one pass over x) -------------------
__global__ __launch_bounds__(256) void gate_split_kernel(
    const float* __restrict__ x,
    const float* __restrict__ g2w, const float* __restrict__ g2b,
    const float* __restrict__ g3w, const float* __restrict__ g3b,
    float* __restrict__ gate,
    __nv_bfloat16* __restrict__ xhi, __nv_bfloat16* __restrict__ xlo, int B)
{
    int row  = (blockIdx.x * 256 + threadIdx.x) >> 5;
    int lane = threadIdx.x & 31;
    if (row >= B) return;

    const float4* xr = reinterpret_cast<const float4*>(x + (size_t)row * IN_DIM);
    float a0 = 0.f, a1 = 0.f, a2 = 0.f, a3 = 0.f;
    #pragma unroll
    for (int j = 0; j < 8; ++j) {
        int i = lane + j * 32;
        float4 v = xr[i];
        int k = i * 4;
        a0 = fmaf(v.x, g2w[k], fmaf(v.y, g2w[k+1], fmaf(v.z, g2w[k+2], fmaf(v.w, g2w[k+3], a0))));
        a1 = fmaf(v.x, g3w[k*3+0], fmaf(v.y, g3w[(k+1)*3+0], fmaf(v.z, g3w[(k+2)*3+0], fmaf(v.w, g3w[(k+3)*3+0], a1))));
        a2 = fmaf(v.x, g3w[k*3+1], fmaf(v.y, g3w[(k+1)*3+1], fmaf(v.z, g3w[(k+2)*3+1], fmaf(v.w, g3w[(k+3)*3+1], a2))));
        a3 = fmaf(v.x, g3w[k*3+2], fmaf(v.y, g3w[(k+1)*3+2], fmaf(v.z, g3w[(k+2)*3+2], fmaf(v.w, g3w[(k+3)*3+2], a3))));
        float vv[4] = {v.x, v.y, v.z, v.w};
        uint32_t ph[2], pl[2];
        #pragma unroll
        for (int q = 0; q < 2; ++q) {
            __nv_bfloat16 h0 = __float2bfloat16(vv[2*q]);
            __nv_bfloat16 h1 = __float2bfloat16(vv[2*q+1]);
            __nv_bfloat16 l0 = __float2bfloat16(vv[2*q]   - __bfloat162float(h0));
            __nv_bfloat16 l1 = __float2bfloat16(vv[2*q+1] - __bfloat162float(h1));
            ph[q] = (uint32_t)__bfloat16_as_ushort(h0) | ((uint32_t)__bfloat16_as_ushort(h1) << 16);
            pl[q] = (uint32_t)__bfloat16_as_ushort(l0) | ((uint32_t)__bfloat16_as_ushort(l1) << 16);
        }
        *reinterpret_cast<uint2*>(xhi + (size_t)row * IN_DIM + k) = make_uint2(ph[0], ph[1]);
        *reinterpret_cast<uint2*>(xlo + (size_t)row * IN_DIM + k) = make_uint2(pl[0], pl[1]);
    }
    #pragma unroll
    for (int off = 16; off > 0; off >>= 1) {
        a0 += __shfl_down_sync(0xffffffffu, a0, off);
        a1 += __shfl_down_sync(0xffffffffu, a1, off);
        a2 += __shfl_down_sync(0xffffffffu, a2, off);
        a3 += __shfl_down_sync(0xffffffffu, a3, off);
    }
    if (lane == 0) {
        float alpha = 1.f / (1.f + expf(-(a0 + g2b[0])));
        float l0 = a1 + g3b[0], l1 = a2 + g3b[1], l2 = a3 + g3b[2];
        float m = fmaxf(l0, fmaxf(l1, l2));
        float e0 = expf(l0 - m), e1 = expf(l1 - m), e2 = expf(l2 - m);
        float inv = 1.f / (e0 + e1 + e2);
        float p0 = e0 * inv, p1 = e1 * inv, p2 = e2 * inv, ga = 1.f - alpha;
        float* o = gate + (size_t)row * N_EXP;
        o[0] = ga * p0;    o[1] = ga * p1;    o[2] = ga * p2;
        o[3] = alpha * p0; o[4] = alpha * p1; o[5] = alpha * p2;
    }
}

// ---------------- transpose + split: src[R,C] fp32 -> dst[C,R] bf16 hi/lo --
__global__ void transplit_kernel(const float* __restrict__ src,
                                 __nv_bfloat16* __restrict__ dhi,
                                 __nv_bfloat16* __restrict__ dlo, int R, int C)
{
    __shared__ float t[32][33];
    size_t zoff = (size_t)blockIdx.z * R * C;
    int c0 = blockIdx.x * 32, r0 = blockIdx.y * 32;
    int tx = threadIdx.x, ty = threadIdx.y;          // 32 x 8
    #pragma unroll
    for (int i = 0; i < 4; ++i)
        t[ty + i*8][tx] = src[zoff + (size_t)(r0 + ty + i*8) * C + c0 + tx];
    __syncthreads();
    #pragma unroll
    for (int i = 0; i < 4; ++i) {
        int c = c0 + ty + i*8, r = r0 + tx;
        float v = t[tx][ty + i*8];
        __nv_bfloat16 h = __float2bfloat16(v);
        __nv_bfloat16 l = __float2bfloat16(v - __bfloat162float(h));
        dhi[zoff + (size_t)c * R + r] = h;
        dlo[zoff + (size_t)c * R + r] = l;
    }
}

// ---------------- split-bf16 HMMA GEMM (mma.sync) ---------------------------
// CTA tile 128x128, BK=32, 8 warps (2M x 4N), warp tile 64x32.
// acc += Ahi*Bhi + Ahi*Blo + Alo*Bhi per K-chunk, fp32 accum in registers.
// 3 stages x 32KB = 96KB smem -> 2 CTAs/SM (16 warps/SM) to fill barrier
// bubbles. launch_bounds(256,2) caps regs at 128; pass order minimizes
// live fragments (Ah dies after pass2, Bl after pass2, Al+Bh only in pass3).
#define BM 128
#define BN 128
#define BK 32
#define STAGES 3
#define STAGE_BYTES 32768   // Ahi 8K | Alo 8K | Bhi 8K | Blo 8K
#define SMEM_TOTAL (STAGES * STAGE_BYTES)

template <int K, bool FIRST>
__global__ __launch_bounds__(256, 2) void gemm_mma(
    const __nv_bfloat16* __restrict__ Ahi, const __nv_bfloat16* __restrict__ Alo,
    const __nv_bfloat16* __restrict__ Bhi, const __nv_bfloat16* __restrict__ Blo,
    const float* __restrict__ bias, const float* __restrict__ gate,
    __nv_bfloat16* __restrict__ Chi, __nv_bfloat16* __restrict__ Clo,
    float* __restrict__ Cf)
{
    extern __shared__ char smem[];
    const uint32_t sbase = smem_u32(smem);
    const int tid  = threadIdx.x;
    const int wid  = tid >> 5;
    const int lane = tid & 31;
    const int mBlk = blockIdx.y * BM;
    const int nBlk = blockIdx.x * BN;
    const int wm = (wid >> 2) * 64;      // warp M offset in tile
    const int wn = (wid & 3) * 32;       // warp N offset in tile
    constexpr int NK = K / BK;

    const __nv_bfloat16* srcTab[4];
    srcTab[0] = Ahi + (size_t)mBlk * K;
    srcTab[1] = Alo + (size_t)mBlk * K;
    srcTab[2] = Bhi + (size_t)nBlk * K;
    srcTab[3] = Blo + (size_t)nBlk * K;

    float acc[4][4][4];
    #pragma unroll
    for (int i = 0; i < 4; ++i)
        #pragma unroll
        for (int j = 0; j < 4; ++j)
            #pragma unroll
            for (int q = 0; q < 4; ++q) acc[i][j][q] = 0.f;

    auto load_stage = [&](int s) {
        const int k0 = s * BK;
        const uint32_t sb = sbase + (s % STAGES) * STAGE_BYTES;
        #pragma unroll
        for (int j = 0; j < 8; ++j) {
            int idx = tid + (j & 3) * 256;           // 0..1023 within region
            int reg = (j >> 2) * 2 + (idx >> 9);     // 0..3: Ahi,Alo,Bhi,Blo
            int row = (idx >> 2) & 127;
            int c   = idx & 3;
            const __nv_bfloat16* src = srcTab[reg] + (size_t)row * K + k0 + c * 8;
            cp16(sb + reg * 8192 + sw_off(row, c), src);
        }
        cp_commit();
    };

    // prologue: stages 0..STAGES-2
    #pragma unroll
    for (int s = 0; s < STAGES - 1; ++s) load_stage(s);

    const int rA = wm + (lane & 15);                       // A ldmatrix row (per mi +16)
    const int rB = wn + ((lane >> 4) << 3) + (lane & 7);   // B ldmatrix row (per pair +16)
    const int cAoff = lane >> 4;                           // A chunk offset
    const int cBoff = (lane >> 3) & 1;                     // B chunk offset

    for (int s = 0; s < NK; ++s) {
        cp_wait<STAGES - 2>();
        __syncthreads();
        // Issue next-stage loads immediately (runs under the MMA burst).
        // Writes slot (s-1)%STAGES, which the sync above just retired.
        if (s + STAGES - 1 < NK) load_stage(s + STAGES - 1);
        else cp_commit();                                   // keep group count uniform

        const uint32_t sb = sbase + (s % STAGES) * STAGE_BYTES;

        #pragma unroll
        for (int kk = 0; kk < 2; ++kk) {
            const int c = kk * 2;
            // ---- pass 1: hi*hi ----
            uint32_t Ah[4][4], Bh[4][2];
            #pragma unroll
            for (int mi = 0; mi < 4; ++mi)
                ldsm4(Ah[mi], sb + sw_off(rA + 16 * mi, c + cAoff));
            #pragma unroll
            for (int jp = 0; jp < 2; ++jp) {
                uint32_t t[4];
                ldsm4(t, sb + 16384 + sw_off(rB + 16 * jp, c + cBoff));
                Bh[2*jp][0] = t[0]; Bh[2*jp][1] = t[1];
                Bh[2*jp+1][0] = t[2]; Bh[2*jp+1][1] = t[3];
            }
            #pragma unroll
            for (int mi = 0; mi < 4; ++mi)
                #pragma unroll
                for (int nj = 0; nj < 4; ++nj)
                    mma_bf16(acc[mi][nj], Ah[mi], Bh[nj]);
            // ---- pass 2: hi*lo (Ah dies after this) ----
            {
                uint32_t Bl[4][2];
                #pragma unroll
                for (int jp = 0; jp < 2; ++jp) {
                    uint32_t t[4];
                    ldsm4(t, sb + 24576 + sw_off(rB + 16 * jp, c + cBoff));
                    Bl[2*jp][0] = t[0]; Bl[2*jp][1] = t[1];
                    Bl[2*jp+1][0] = t[2]; Bl[2*jp+1][1] = t[3];
                }
                #pragma unroll
                for (int mi = 0; mi < 4; ++mi)
                    #pragma unroll
                    for (int nj = 0; nj < 4; ++nj)
                        mma_bf16(acc[mi][nj], Ah[mi], Bl[nj]);
            }
            // ---- pass 3: lo*hi (reuses Bh; Ah/Bl registers free) ----
            {
                uint32_t Al[4][4];
                #pragma unroll
                for (int mi = 0; mi < 4; ++mi)
                    ldsm4(Al[mi], sb + 8192 + sw_off(rA + 16 * mi, c + cAoff));
                #pragma unroll
                for (int mi = 0; mi < 4; ++mi)
                    #pragma unroll
                    for (int nj = 0; nj < 4; ++nj)
                        mma_bf16(acc[mi][nj], Al[mi], Bh[nj]);
            }
        }
    }

    // ---- epilogue ----
    if constexpr (FIRST) {
        const int e = nBlk >> 9;
        #pragma unroll
        for (int mi = 0; mi < 4; ++mi)
            #pragma unroll
            for (int h = 0; h < 2; ++h) {
                const int row = mBlk + wm + 16 * mi + (lane >> 2) + 8 * h;
                const float g = gate[(size_t)row * N_EXP + e];
                #pragma unroll
                for (int nj = 0; nj < 4; ++nj) {
                    const int col = nBlk + wn + 8 * nj + 2 * (lane & 3);
                    const int bc = e * HID_DIM + (col & (HID_DIM - 1));
                    float v0 = acc[mi][nj][2*h]   + bias[bc];
                    float v1 = acc[mi][nj][2*h+1] + bias[bc + 1];
                    v0 = fmaxf(v0, 0.f) * g;
                    v1 = fmaxf(v1, 0.f) * g;
                    __nv_bfloat16 h0 = __float2bfloat16(v0);
                    __nv_bfloat16 h1 = __float2bfloat16(v1);
                    __nv_bfloat16 l0 = __float2bfloat16(v0 - __bfloat162float(h0));
                    __nv_bfloat16 l1 = __float2bfloat16(v1 - __bfloat162float(h1));
                    uint32_t ph = (uint32_t)__bfloat16_as_ushort(h0) | ((uint32_t)__bfloat16_as_ushort(h1) << 16);
                    uint32_t pl = (uint32_t)__bfloat16_as_ushort(l0) | ((uint32_t)__bfloat16_as_ushort(l1) << 16);
                    *reinterpret_cast<uint32_t*>(Chi + (size_t)row * H3 + col) = ph;
                    *reinterpret_cast<uint32_t*>(Clo + (size_t)row * H3 + col) = pl;
                }
            }
    } else {
        #pragma unroll
        for (int mi = 0; mi < 4; ++mi)
            #pragma unroll
            for (int h = 0; h < 2; ++h) {
                const int row = mBlk + wm + 16 * mi + (lane >> 2) + 8 * h;
                float gw[N_EXP];
                #pragma unroll
                for (int q = 0; q < N_EXP; ++q) gw[q] = gate[(size_t)row * N_EXP + q];
                #pragma unroll
                for (int nj = 0; nj < 4; ++nj) {
                    const int col = nBlk + wn + 8 * nj + 2 * (lane & 3);
                    float v0 = acc[mi][nj][2*h];
                    float v1 = acc[mi][nj][2*h+1];
                    #pragma unroll
                    for (int q = 0; q < N_EXP; ++q) {
                        v0 = fmaf(gw[q], bias[q * OUT_DIM + col],     v0);
                        v1 = fmaf(gw[q], bias[q * OUT_DIM + col + 1], v1);
                    }
                    *reinterpret_cast<float2*>(Cf + (size_t)row * OUT_DIM + col) = make_float2(v0, v1);
                }
            }
    }
}

// ---------------------------------------------------------------------------
extern "C" void kernel_launch(void* const* d_in, const int* in_sizes, int n_in,
                              void* d_out, int out_size)
{
    const float* x   = (const float*)d_in[0];
    const float* g2w = (const float*)d_in[1];
    const float* g2b = (const float*)d_in[2];
    const float* g3w = (const float*)d_in[3];
    const float* g3b = (const float*)d_in[4];
    const float* w1  = (const float*)d_in[5];
    const float* b1  = (const float*)d_in[6];
    const float* w2  = (const float*)d_in[7];
    const float* b2  = (const float*)d_in[8];
    float* out = (float*)d_out;

    const int B = in_sizes[0] / IN_DIM;   // 32768

    float *gate; __nv_bfloat16 *xhi, *xlo, *w1hi, *w1lo, *w2hi, *w2lo, *hshi, *hslo;
    cudaGetSymbolAddress((void**)&gate, g_gate);
    cudaGetSymbolAddress((void**)&xhi, g_xhi);
    cudaGetSymbolAddress((void**)&xlo, g_xlo);
    cudaGetSymbolAddress((void**)&w1hi, g_w1hi);
    cudaGetSymbolAddress((void**)&w1lo, g_w1lo);
    cudaGetSymbolAddress((void**)&w2hi, g_w2hi);
    cudaGetSymbolAddress((void**)&w2lo, g_w2lo);
    cudaGetSymbolAddress((void**)&hshi, g_hshi);
    cudaGetSymbolAddress((void**)&hslo, g_hslo);

    cudaFuncSetAttribute(gemm_mma<IN_DIM, true>,
                         cudaFuncAttributeMaxDynamicSharedMemorySize, SMEM_TOTAL);
    cudaFuncSetAttribute(gemm_mma<H3, false>,
                         cudaFuncAttributeMaxDynamicSharedMemorySize, SMEM_TOTAL);

    // 1) gate + split x (single pass over x)
    gate_split_kernel<<<(B + 7) / 8, 256>>>(x, g2w, g2b, g3w, g3b, gate, xhi, xlo, B);

    // 2) transpose+split weights
    transplit_kernel<<<dim3(HID_DIM/32, IN_DIM/32, N_EXP), dim3(32, 8)>>>(w1, w1hi, w1lo, IN_DIM, HID_DIM);
    transplit_kernel<<<dim3(OUT_DIM/32, H3/32, 1),        dim3(32, 8)>>>(w2, w2hi, w2lo, H3, OUT_DIM);

    // 3) hs = split(relu(x @ W1 + b1) * gate)   [B,3072] bf16 hi/lo
    gemm_mma<IN_DIM, true><<<dim3(H3/BN, B/BM), 256, SMEM_TOTAL>>>(
        xhi, xlo, w1hi, w1lo, b1, gate, hshi, hslo, nullptr);

    // 4) out = hs @ W2 + gate @ b2              [B,1024] fp32
    gemm_mma<H3, false><<<dim3(OUT_DIM/BN, B/BM), 256, SMEM_TOTAL>>>(
        hshi, hslo, w2hi, w2lo, b2, gate, nullptr, nullptr, out);
}

// round 7
// speedup vs baseline: 3.7245x; 1.0900x over previous
#include <cuda_runtime.h>
#include <cuda_bf16.h>
#include <cstdint>
#include <cstddef>

#define IN_DIM   1024
#define HID_DIM  512
#define OUT_DIM  1024
#define N_EXP    6
#define H3       3072
#define MAXB     32768

// ---------------- scratch (device globals; no allocation allowed) ----------
__device__ float         g_gate[(size_t)MAXB * N_EXP];
__device__ __nv_bfloat16 g_xhi [(size_t)MAXB * IN_DIM];
__device__ __nv_bfloat16 g_xlo [(size_t)MAXB * IN_DIM];
__device__ __nv_bfloat16 g_w1hi[(size_t)H3 * IN_DIM];    // [3072,1024] N-major, K contig
__device__ __nv_bfloat16 g_w1lo[(size_t)H3 * IN_DIM];
__device__ __nv_bfloat16 g_w2hi[(size_t)OUT_DIM * H3];   // [1024,3072]
__device__ __nv_bfloat16 g_w2lo[(size_t)OUT_DIM * H3];
__device__ __nv_bfloat16 g_hshi[(size_t)MAXB * H3];
__device__ __nv_bfloat16 g_hslo[(size_t)MAXB * H3];

// ---------------- helpers ---------------------------------------------------
__device__ __forceinline__ uint32_t smem_u32(const void* p) {
    uint32_t a;
    asm("{ .reg .u64 t; cvta.to.shared.u64 t, %1; cvt.u32.u64 %0, t; }" : "=r"(a) : "l"(p));
    return a;
}
__device__ __forceinline__ void cp16(uint32_t dst, const void* src) {
    asm volatile("cp.async.cg.shared.global [%0], [%1], 16;" :: "r"(dst), "l"(src));
}
__device__ __forceinline__ void cp_commit() {
    asm volatile("cp.async.commit_group;" ::: "memory");
}
template <int N>
__device__ __forceinline__ void cp_wait() {
    asm volatile("cp.async.wait_group %0;" :: "n"(N) : "memory");
}
__device__ __forceinline__ void ldsm4(uint32_t* r, uint32_t addr) {
    asm volatile("ldmatrix.sync.aligned.m8n8.x4.shared.b16 {%0,%1,%2,%3}, [%4];"
                 : "=r"(r[0]), "=r"(r[1]), "=r"(r[2]), "=r"(r[3]) : "r"(addr));
}
__device__ __forceinline__ void mma_bf16(float* c, const uint32_t* a, const uint32_t* b) {
    asm volatile(
        "mma.sync.aligned.m16n8k16.row.col.f32.bf16.bf16.f32 "
        "{%0,%1,%2,%3}, {%4,%5,%6,%7}, {%8,%9}, {%0,%1,%2,%3};"
        : "+f"(c[0]), "+f"(c[1]), "+f"(c[2]), "+f"(c[3])
        : "r"(a[0]), "r"(a[1]), "r"(a[2]), "r"(a[3]), "r"(b[0]), "r"(b[1]));
}
// 64B rows, 16B chunks, xor-swizzle so any 8 consecutive rows at fixed chunk
// index hit 8 distinct 16B slots mod 128B (conflict-free ldmatrix).
__device__ __forceinline__ int sw_off(int row, int chunk) {
    return row * 64 + ((chunk ^ ((row >> 1) & 3)) << 4);
}

// ---------------- fused gate + x split (one pass over x) -------------------
__global__ __launch_bounds__(256) void gate_split_kernel(
    const float* __restrict__ x,
    const float* __restrict__ g2w, const float* __restrict__ g2b,
    const float* __restrict__ g3w, const float* __restrict__ g3b,
    float* __restrict__ gate,
    __nv_bfloat16* __restrict__ xhi, __nv_bfloat16* __restrict__ xlo, int B)
{
    int row  = (blockIdx.x * 256 + threadIdx.x) >> 5;
    int lane = threadIdx.x & 31;
    if (row >= B) return;

    const float4* xr = reinterpret_cast<const float4*>(x + (size_t)row * IN_DIM);
    float a0 = 0.f, a1 = 0.f, a2 = 0.f, a3 = 0.f;
    #pragma unroll
    for (int j = 0; j < 8; ++j) {
        int i = lane + j * 32;
        float4 v = xr[i];
        int k = i * 4;
        a0 = fmaf(v.x, g2w[k], fmaf(v.y, g2w[k+1], fmaf(v.z, g2w[k+2], fmaf(v.w, g2w[k+3], a0))));
        a1 = fmaf(v.x, g3w[k*3+0], fmaf(v.y, g3w[(k+1)*3+0], fmaf(v.z, g3w[(k+2)*3+0], fmaf(v.w, g3w[(k+3)*3+0], a1))));
        a2 = fmaf(v.x, g3w[k*3+1], fmaf(v.y, g3w[(k+1)*3+1], fmaf(v.z, g3w[(k+2)*3+1], fmaf(v.w, g3w[(k+3)*3+1], a2))));
        a3 = fmaf(v.x, g3w[k*3+2], fmaf(v.y, g3w[(k+1)*3+2], fmaf(v.z, g3w[(k+2)*3+2], fmaf(v.w, g3w[(k+3)*3+2], a3))));
        float vv[4] = {v.x, v.y, v.z, v.w};
        uint32_t ph[2], pl[2];
        #pragma unroll
        for (int q = 0; q < 2; ++q) {
            __nv_bfloat16 h0 = __float2bfloat16(vv[2*q]);
            __nv_bfloat16 h1 = __float2bfloat16(vv[2*q+1]);
            __nv_bfloat16 l0 = __float2bfloat16(vv[2*q]   - __bfloat162float(h0));
            __nv_bfloat16 l1 = __float2bfloat16(vv[2*q+1] - __bfloat162float(h1));
            ph[q] = (uint32_t)__bfloat16_as_ushort(h0) | ((uint32_t)__bfloat16_as_ushort(h1) << 16);
            pl[q] = (uint32_t)__bfloat16_as_ushort(l0) | ((uint32_t)__bfloat16_as_ushort(l1) << 16);
        }
        *reinterpret_cast<uint2*>(xhi + (size_t)row * IN_DIM + k) = make_uint2(ph[0], ph[1]);
        *reinterpret_cast<uint2*>(xlo + (size_t)row * IN_DIM + k) = make_uint2(pl[0], pl[1]);
    }
    #pragma unroll
    for (int off = 16; off > 0; off >>= 1) {
        a0 += __shfl_down_sync(0xffffffffu, a0, off);
        a1 += __shfl_down_sync(0xffffffffu, a1, off);
        a2 += __shfl_down_sync(0xffffffffu, a2, off);
        a3 += __shfl_down_sync(0xffffffffu, a3, off);
    }
    if (lane == 0) {
        float alpha = 1.f / (1.f + expf(-(a0 + g2b[0])));
        float l0 = a1 + g3b[0], l1 = a2 + g3b[1], l2 = a3 + g3b[2];
        float m = fmaxf(l0, fmaxf(l1, l2));
        float e0 = expf(l0 - m), e1 = expf(l1 - m), e2 = expf(l2 - m);
        float inv = 1.f / (e0 + e1 + e2);
        float p0 = e0 * inv, p1 = e1 * inv, p2 = e2 * inv, ga = 1.f - alpha;
        float* o = gate + (size_t)row * N_EXP;
        o[0] = ga * p0;    o[1] = ga * p1;    o[2] = ga * p2;
        o[3] = alpha * p0; o[4] = alpha * p1; o[5] = alpha * p2;
    }
}

// ---------------- transpose + split: src[R,C] fp32 -> dst[C,R] bf16 hi/lo --
__global__ void transplit_kernel(const float* __restrict__ src,
                                 __nv_bfloat16* __restrict__ dhi,
                                 __nv_bfloat16* __restrict__ dlo, int R, int C)
{
    __shared__ float t[32][33];
    size_t zoff = (size_t)blockIdx.z * R * C;
    int c0 = blockIdx.x * 32, r0 = blockIdx.y * 32;
    int tx = threadIdx.x, ty = threadIdx.y;          // 32 x 8
    #pragma unroll
    for (int i = 0; i < 4; ++i)
        t[ty + i*8][tx] = src[zoff + (size_t)(r0 + ty + i*8) * C + c0 + tx];
    __syncthreads();
    #pragma unroll
    for (int i = 0; i < 4; ++i) {
        int c = c0 + ty + i*8, r = r0 + tx;
        float v = t[tx][ty + i*8];
        __nv_bfloat16 h = __float2bfloat16(v);
        __nv_bfloat16 l = __float2bfloat16(v - __bfloat162float(h));
        dhi[zoff + (size_t)c * R + r] = h;
        dlo[zoff + (size_t)c * R + r] = l;
    }
}

// ---------------- split-bf16 HMMA GEMM (mma.sync) ---------------------------
// CTA tile 128x128, BK=32, 8 warps (2M x 4N), warp tile 64x32.
// acc += Ahi*Bhi + Ahi*Blo + Alo*Bhi per K-chunk, fp32 accum in registers.
// 3 stages x 32KB, 2 CTAs/SM. ldsm of kk0 hi-frags issued BEFORE next-stage
// cp.async so tensor pipe restarts immediately after the barrier; Ah(kk1)
// reload overlaps pass-3 MMAs; #pragma unroll 3 keeps code size inside I$.
#define BM 128
#define BN 128
#define BK 32
#define STAGES 3
#define STAGE_BYTES 32768   // Ahi 8K | Alo 8K | Bhi 8K | Blo 8K
#define SMEM_TOTAL (STAGES * STAGE_BYTES)

template <int K, bool FIRST>
__global__ __launch_bounds__(256, 2) void gemm_mma(
    const __nv_bfloat16* __restrict__ Ahi, const __nv_bfloat16* __restrict__ Alo,
    const __nv_bfloat16* __restrict__ Bhi, const __nv_bfloat16* __restrict__ Blo,
    const float* __restrict__ bias, const float* __restrict__ gate,
    __nv_bfloat16* __restrict__ Chi, __nv_bfloat16* __restrict__ Clo,
    float* __restrict__ Cf)
{
    extern __shared__ char smem[];
    const uint32_t sbase = smem_u32(smem);
    const int tid  = threadIdx.x;
    const int wid  = tid >> 5;
    const int lane = tid & 31;
    const int mBlk = blockIdx.y * BM;
    const int nBlk = blockIdx.x * BN;
    const int wm = (wid >> 2) * 64;      // warp M offset in tile
    const int wn = (wid & 3) * 32;       // warp N offset in tile
    constexpr int NK = K / BK;

    const __nv_bfloat16* srcTab[4];
    srcTab[0] = Ahi + (size_t)mBlk * K;
    srcTab[1] = Alo + (size_t)mBlk * K;
    srcTab[2] = Bhi + (size_t)nBlk * K;
    srcTab[3] = Blo + (size_t)nBlk * K;

    float acc[4][4][4];
    #pragma unroll
    for (int i = 0; i < 4; ++i)
        #pragma unroll
        for (int j = 0; j < 4; ++j)
            #pragma unroll
            for (int q = 0; q < 4; ++q) acc[i][j][q] = 0.f;

    auto load_stage = [&](int s) {
        const int k0 = s * BK;
        const uint32_t sb = sbase + (s % STAGES) * STAGE_BYTES;
        #pragma unroll
        for (int j = 0; j < 8; ++j) {
            int idx = tid + (j & 3) * 256;           // 0..1023 within region
            int reg = (j >> 2) * 2 + (idx >> 9);     // 0..3: Ahi,Alo,Bhi,Blo
            int row = (idx >> 2) & 127;
            int c   = idx & 3;
            const __nv_bfloat16* src = srcTab[reg] + (size_t)row * K + k0 + c * 8;
            cp16(sb + reg * 8192 + sw_off(row, c), src);
        }
        cp_commit();
    };

    // prologue: stages 0..STAGES-2
    #pragma unroll
    for (int s = 0; s < STAGES - 1; ++s) load_stage(s);

    const int rA = wm + (lane & 15);                       // A ldmatrix row (per mi +16)
    const int rB = wn + ((lane >> 4) << 3) + (lane & 7);   // B ldmatrix row (per pair +16)
    const int cAoff = lane >> 4;                           // A chunk offset
    const int cBoff = (lane >> 3) & 1;                     // B chunk offset

    #pragma unroll 3
    for (int s = 0; s < NK; ++s) {
        cp_wait<STAGES - 2>();
        __syncthreads();
        const uint32_t sb = sbase + (s % STAGES) * STAGE_BYTES;

        // --- restart tensor pipe first: kk0 hi fragments ---
        uint32_t Ah[4][4], Bh[4][2];
        #pragma unroll
        for (int mi = 0; mi < 4; ++mi)
            ldsm4(Ah[mi], sb + sw_off(rA + 16 * mi, cAoff));
        #pragma unroll
        for (int jp = 0; jp < 2; ++jp) {
            uint32_t t[4];
            ldsm4(t, sb + 16384 + sw_off(rB + 16 * jp, cBoff));
            Bh[2*jp][0] = t[0]; Bh[2*jp][1] = t[1];
            Bh[2*jp+1][0] = t[2]; Bh[2*jp+1][1] = t[3];
        }

        // next-stage global loads issue after the first ldsm batch
        if (s + STAGES - 1 < NK) load_stage(s + STAGES - 1);
        else cp_commit();                                   // keep group count uniform

        #pragma unroll
        for (int kk = 0; kk < 2; ++kk) {
            const int c = kk * 2;
            // ---- pass 1: hi*hi ----
            #pragma unroll
            for (int mi = 0; mi < 4; ++mi)
                #pragma unroll
                for (int nj = 0; nj < 4; ++nj)
                    mma_bf16(acc[mi][nj], Ah[mi], Bh[nj]);
            // ---- pass 2: hi*lo ----
            uint32_t Bl[4][2];
            #pragma unroll
            for (int jp = 0; jp < 2; ++jp) {
                uint32_t t[4];
                ldsm4(t, sb + 24576 + sw_off(rB + 16 * jp, c + cBoff));
                Bl[2*jp][0] = t[0]; Bl[2*jp][1] = t[1];
                Bl[2*jp+1][0] = t[2]; Bl[2*jp+1][1] = t[3];
            }
            #pragma unroll
            for (int mi = 0; mi < 4; ++mi)
                #pragma unroll
                for (int nj = 0; nj < 4; ++nj)
                    mma_bf16(acc[mi][nj], Ah[mi], Bl[nj]);
            // Ah dead -> prefetch Ah(kk1) under pass-3 MMAs
            uint32_t Al[4][4];
            #pragma unroll
            for (int mi = 0; mi < 4; ++mi)
                ldsm4(Al[mi], sb + 8192 + sw_off(rA + 16 * mi, c + cAoff));
            if (kk == 0) {
                #pragma unroll
                for (int mi = 0; mi < 4; ++mi)
                    ldsm4(Ah[mi], sb + sw_off(rA + 16 * mi, 2 + cAoff));
            }
            // ---- pass 3: lo*hi ----
            #pragma unroll
            for (int mi = 0; mi < 4; ++mi)
                #pragma unroll
                for (int nj = 0; nj < 4; ++nj)
                    mma_bf16(acc[mi][nj], Al[mi], Bh[nj]);
            // Bh(kk0) dead -> load Bh(kk1)
            if (kk == 0) {
                #pragma unroll
                for (int jp = 0; jp < 2; ++jp) {
                    uint32_t t[4];
                    ldsm4(t, sb + 16384 + sw_off(rB + 16 * jp, 2 + cBoff));
                    Bh[2*jp][0] = t[0]; Bh[2*jp][1] = t[1];
                    Bh[2*jp+1][0] = t[2]; Bh[2*jp+1][1] = t[3];
                }
            }
        }
    }

    // ---- epilogue ----
    if constexpr (FIRST) {
        const int e = nBlk >> 9;
        // hoist bias per column (8 values, row-invariant)
        float bcol[8];
        #pragma unroll
        for (int nj = 0; nj < 4; ++nj) {
            const int col = nBlk + wn + 8 * nj + 2 * (lane & 3);
            const int bc = e * HID_DIM + (col & (HID_DIM - 1));
            bcol[2*nj]   = bias[bc];
            bcol[2*nj+1] = bias[bc + 1];
        }
        #pragma unroll
        for (int mi = 0; mi < 4; ++mi)
            #pragma unroll
            for (int h = 0; h < 2; ++h) {
                const int row = mBlk + wm + 16 * mi + (lane >> 2) + 8 * h;
                const float g = gate[(size_t)row * N_EXP + e];
                #pragma unroll
                for (int nj = 0; nj < 4; ++nj) {
                    const int col = nBlk + wn + 8 * nj + 2 * (lane & 3);
                    float v0 = acc[mi][nj][2*h]   + bcol[2*nj];
                    float v1 = acc[mi][nj][2*h+1] + bcol[2*nj+1];
                    v0 = fmaxf(v0, 0.f) * g;
                    v1 = fmaxf(v1, 0.f) * g;
                    __nv_bfloat16 h0 = __float2bfloat16(v0);
                    __nv_bfloat16 h1 = __float2bfloat16(v1);
                    __nv_bfloat16 l0 = __float2bfloat16(v0 - __bfloat162float(h0));
                    __nv_bfloat16 l1 = __float2bfloat16(v1 - __bfloat162float(h1));
                    uint32_t ph = (uint32_t)__bfloat16_as_ushort(h0) | ((uint32_t)__bfloat16_as_ushort(h1) << 16);
                    uint32_t pl = (uint32_t)__bfloat16_as_ushort(l0) | ((uint32_t)__bfloat16_as_ushort(l1) << 16);
                    *reinterpret_cast<uint32_t*>(Chi + (size_t)row * H3 + col) = ph;
                    *reinterpret_cast<uint32_t*>(Clo + (size_t)row * H3 + col) = pl;
                }
            }
    } else {
        // hoist bias[q][col] for the 8 columns this thread owns: 48 LDG total
        float bb[8][N_EXP];
        #pragma unroll
        for (int nj = 0; nj < 4; ++nj) {
            const int col = nBlk + wn + 8 * nj + 2 * (lane & 3);
            #pragma unroll
            for (int q = 0; q < N_EXP; ++q) {
                bb[2*nj][q]   = bias[q * OUT_DIM + col];
                bb[2*nj+1][q] = bias[q * OUT_DIM + col + 1];
            }
        }
        #pragma unroll
        for (int mi = 0; mi < 4; ++mi)
            #pragma unroll
            for (int h = 0; h < 2; ++h) {
                const int row = mBlk + wm + 16 * mi + (lane >> 2) + 8 * h;
                // gate row: 24-byte stride, 8B aligned -> 3x float2
                const float2* gp = reinterpret_cast<const float2*>(gate + (size_t)row * N_EXP);
                float2 gA = gp[0], gB = gp[1], gC = gp[2];
                float gw[N_EXP] = {gA.x, gA.y, gB.x, gB.y, gC.x, gC.y};
                #pragma unroll
                for (int nj = 0; nj < 4; ++nj) {
                    const int col = nBlk + wn + 8 * nj + 2 * (lane & 3);
                    float v0 = acc[mi][nj][2*h];
                    float v1 = acc[mi][nj][2*h+1];
                    #pragma unroll
                    for (int q = 0; q < N_EXP; ++q) {
                        v0 = fmaf(gw[q], bb[2*nj][q],   v0);
                        v1 = fmaf(gw[q], bb[2*nj+1][q], v1);
                    }
                    *reinterpret_cast<float2*>(Cf + (size_t)row * OUT_DIM + col) = make_float2(v0, v1);
                }
            }
    }
}

// ---------------------------------------------------------------------------
extern "C" void kernel_launch(void* const* d_in, const int* in_sizes, int n_in,
                              void* d_out, int out_size)
{
    const float* x   = (const float*)d_in[0];
    const float* g2w = (const float*)d_in[1];
    const float* g2b = (const float*)d_in[2];
    const float* g3w = (const float*)d_in[3];
    const float* g3b = (const float*)d_in[4];
    const float* w1  = (const float*)d_in[5];
    const float* b1  = (const float*)d_in[6];
    const float* w2  = (const float*)d_in[7];
    const float* b2  = (const float*)d_in[8];
    float* out = (float*)d_out;

    const int B = in_sizes[0] / IN_DIM;   // 32768

    float *gate; __nv_bfloat16 *xhi, *xlo, *w1hi, *w1lo, *w2hi, *w2lo, *hshi, *hslo;
    cudaGetSymbolAddress((void**)&gate, g_gate);
    cudaGetSymbolAddress((void**)&xhi, g_xhi);
    cudaGetSymbolAddress((void**)&xlo, g_xlo);
    cudaGetSymbolAddress((void**)&w1hi, g_w1hi);
    cudaGetSymbolAddress((void**)&w1lo, g_w1lo);
    cudaGetSymbolAddress((void**)&w2hi, g_w2hi);
    cudaGetSymbolAddress((void**)&w2lo, g_w2lo);
    cudaGetSymbolAddress((void**)&hshi, g_hshi);
    cudaGetSymbolAddress((void**)&hslo, g_hslo);

    cudaFuncSetAttribute(gemm_mma<IN_DIM, true>,
                         cudaFuncAttributeMaxDynamicSharedMemorySize, SMEM_TOTAL);
    cudaFuncSetAttribute(gemm_mma<H3, false>,
                         cudaFuncAttributeMaxDynamicSharedMemorySize, SMEM_TOTAL);

    // 1) gate + split x (single pass over x)
    gate_split_kernel<<<(B + 7) / 8, 256>>>(x, g2w, g2b, g3w, g3b, gate, xhi, xlo, B);

    // 2) transpose+split weights
    transplit_kernel<<<dim3(HID_DIM/32, IN_DIM/32, N_EXP), dim3(32, 8)>>>(w1, w1hi, w1lo, IN_DIM, HID_DIM);
    transplit_kernel<<<dim3(OUT_DIM/32, H3/32, 1),        dim3(32, 8)>>>(w2, w2hi, w2lo, H3, OUT_DIM);

    // 3) hs = split(relu(x @ W1 + b1) * gate)   [B,3072] bf16 hi/lo
    gemm_mma<IN_DIM, true><<<dim3(H3/BN, B/BM), 256, SMEM_TOTAL>>>(
        xhi, xlo, w1hi, w1lo, b1, gate, hshi, hslo, nullptr);

    // 4) out = hs @ W2 + gate @ b2              [B,1024] fp32
    gemm_mma<H3, false><<<dim3(OUT_DIM/BN, B/BM), 256, SMEM_TOTAL>>>(
        hshi, hslo, w2hi, w2lo, b2, gate, nullptr, nullptr, out);
}